// round 8
// baseline (speedup 1.0000x reference)
#include <cuda_runtime.h>

// ---------------------------------------------------------------------------
// SpatialRangeAttention — GB300 sm_103a
// ---------------------------------------------------------------------------

#define BB   2
#define CC   64
#define HH   112
#define WW   112
#define HWP  (HH*WW)      // 12544
#define NPIX (BB*HWP)     // 25088
#define N2   49

typedef unsigned long long u64;

__device__ __forceinline__ void fma2(u64 &d, u64 a, u64 b) {
    asm("fma.rn.f32x2 %0, %1, %2, %0;" : "+l"(d) : "l"(a), "l"(b));
}
__device__ __forceinline__ u64 pk2(float a, float b) {
    u64 r; asm("mov.b64 %0, {%1,%2};" : "=l"(r) : "f"(a), "f"(b)); return r;
}
__device__ __forceinline__ float2 unpk(u64 v) {
    float2 r; asm("mov.b64 {%0,%1}, %2;" : "=f"(r.x), "=f"(r.y) : "l"(v)); return r;
}

// Scratch
__device__ float g_sem_t[NPIX*CC];   // semantic transposed [pix][c]
__device__ float g_spa_t[NPIX*CC];   // spatial  transposed [pix][c]
__device__ float g_px_cm[NPIX*CC];   // range-projected, CHANNEL-major [b][c][hw]
__device__ float g_nrm[NPIX];        // per-pixel ||px||^2
__device__ float g_comb[NPIX*N2];    // bilateral / final weights [pix][n]

// ---------------------------------------------------------------------------
// K0: transpose both inputs [B,C,HW] -> [B*HW, C]
// ---------------------------------------------------------------------------
__global__ __launch_bounds__(256) void k_transpose2(
    const float* __restrict__ sem, const float* __restrict__ spa)
{
    __shared__ float t1[32][33];
    __shared__ float t2[32][33];
    int b  = blockIdx.z;
    int c0 = blockIdx.y * 32;
    int p0 = blockIdx.x * 32;
    int tx = threadIdx.x, ty = threadIdx.y;
    #pragma unroll
    for (int i = ty; i < 32; i += 8) {
        int c = c0 + i, p = p0 + tx;
        t1[i][tx] = sem[(b*CC + c)*HWP + p];
        t2[i][tx] = spa[(b*CC + c)*HWP + p];
    }
    __syncthreads();
    #pragma unroll
    for (int i = ty; i < 32; i += 8) {
        int p = p0 + i, c = c0 + tx;
        g_sem_t[(b*HWP + p)*CC + c] = t1[tx][i];
        g_spa_t[(b*HWP + p)*CC + c] = t2[tx][i];
    }
}

// ---------------------------------------------------------------------------
// K1: range_proj: conv -> LN -> SiLU -> conv. 2 px/warp, f32x2 FMA.
// Outputs channel-major px + norms. smem 41984B, grid NPIX/16.
// ---------------------------------------------------------------------------
__global__ __launch_bounds__(256, 5) void k_range(
    const float* __restrict__ w1, const float* __restrict__ b1,
    const float* __restrict__ g,  const float* __restrict__ be,
    const float* __restrict__ w2, const float* __restrict__ b2)
{
    extern __shared__ float sm[];
    float2* W1v = (float2*)sm;              // [64][32] f2 (pair = out o,o+32)
    float2* W2v = (float2*)(sm + 4096);
    float*  b1s = sm + 8192;
    float*  gs  = sm + 8256;
    float*  bes = sm + 8320;
    float*  b2s = sm + 8384;
    float*  xs  = sm + 8448;                // [8 warps][64 rows][4] dup: x0,x0,x1,x1
    int tid = threadIdx.x, lane = tid & 31, w = tid >> 5;

    for (int i = tid; i < 2048; i += 256) {
        int c = i >> 5, l = i & 31;
        W1v[i] = make_float2(w1[l*64 + c], w1[(l+32)*64 + c]);
        W2v[i] = make_float2(w2[l*64 + c], w2[(l+32)*64 + c]);
    }
    if (tid < 64) { b1s[tid]=b1[tid]; gs[tid]=g[tid]; bes[tid]=be[tid]; b2s[tid]=b2[tid]; }

    int pbase = blockIdx.x * 16 + w * 2;
    float* xw = xs + w * 256;

    {
        float xa0 = g_sem_t[(pbase+0)*CC + lane];
        float xa1 = g_sem_t[(pbase+1)*CC + lane];
        float xb0 = g_sem_t[(pbase+0)*CC + lane + 32];
        float xb1 = g_sem_t[(pbase+1)*CC + lane + 32];
        *(float4*)&xw[lane*4]      = make_float4(xa0, xa0, xa1, xa1);
        *(float4*)&xw[(lane+32)*4] = make_float4(xb0, xb0, xb1, xb1);
    }
    __syncthreads();

    u64 acc0 = pk2(b1s[lane], b1s[lane+32]);
    u64 acc1 = acc0;
    #pragma unroll 8
    for (int c = 0; c < 64; c++) {
        u64 a = *(const u64*)&W1v[c*32 + lane];
        ulonglong2 xp = *(const ulonglong2*)(xw + c*4);
        fma2(acc0, a, xp.x);
        fma2(acc1, a, xp.y);
    }

    // LN + SiLU per pixel (channels: lane, lane+32), dup writeback
    {
        float2 yA = unpk(acc0), yB = unpk(acc1);
        float h0A, h1A, h0B, h1B;
        {
            float s = yA.x + yA.y, t = yA.x*yA.x + yA.y*yA.y;
            #pragma unroll
            for (int o = 16; o; o >>= 1) {
                s += __shfl_xor_sync(0xffffffffu, s, o);
                t += __shfl_xor_sync(0xffffffffu, t, o);
            }
            float mean = s * (1.f/64.f);
            float rstd = rsqrtf(t * (1.f/64.f) - mean*mean + 1e-6f);
            float a0 = gs[lane]    * (yA.x-mean) * rstd + bes[lane];
            float a1 = gs[lane+32] * (yA.y-mean) * rstd + bes[lane+32];
            h0A = a0 / (1.f + __expf(-a0));
            h1A = a1 / (1.f + __expf(-a1));
        }
        {
            float s = yB.x + yB.y, t = yB.x*yB.x + yB.y*yB.y;
            #pragma unroll
            for (int o = 16; o; o >>= 1) {
                s += __shfl_xor_sync(0xffffffffu, s, o);
                t += __shfl_xor_sync(0xffffffffu, t, o);
            }
            float mean = s * (1.f/64.f);
            float rstd = rsqrtf(t * (1.f/64.f) - mean*mean + 1e-6f);
            float a0 = gs[lane]    * (yB.x-mean) * rstd + bes[lane];
            float a1 = gs[lane+32] * (yB.y-mean) * rstd + bes[lane+32];
            h0B = a0 / (1.f + __expf(-a0));
            h1B = a1 / (1.f + __expf(-a1));
        }
        __syncwarp();
        *(float4*)&xw[lane*4]      = make_float4(h0A, h0A, h0B, h0B);
        *(float4*)&xw[(lane+32)*4] = make_float4(h1A, h1A, h1B, h1B);
        __syncwarp();
    }

    acc0 = pk2(b2s[lane], b2s[lane+32]);
    acc1 = acc0;
    #pragma unroll 8
    for (int c = 0; c < 64; c++) {
        u64 a = *(const u64*)&W2v[c*32 + lane];
        ulonglong2 xp = *(const ulonglong2*)(xw + c*4);
        fma2(acc0, a, xp.x);
        fma2(acc1, a, xp.y);
    }

    float2 yA = unpk(acc0), yB = unpk(acc1);
    // norms
    {
        float t = yA.x*yA.x + yA.y*yA.y;
        #pragma unroll
        for (int o = 16; o; o >>= 1) t += __shfl_xor_sync(0xffffffffu, t, o);
        if (lane == 0) g_nrm[pbase] = t;
        float u = yB.x*yB.x + yB.y*yB.y;
        #pragma unroll
        for (int o = 16; o; o >>= 1) u += __shfl_xor_sync(0xffffffffu, u, o);
        if (lane == 0) g_nrm[pbase + 1] = u;
    }
    // channel-major stores (2 consecutive pixels -> float2)
    {
        int b = pbase / HWP, pp = pbase % HWP;
        *(float2*)&g_px_cm[(size_t)(b*CC + lane)*HWP + pp]      = make_float2(yA.x, yB.x);
        *(float2*)&g_px_cm[(size_t)(b*CC + lane + 32)*HWP + pp] = make_float2(yA.y, yB.y);
    }
}

// ---------------------------------------------------------------------------
// K2: bilateral via dot-form: dist2 = |n|^2+|c|^2-2dot. Warp = (32 pixels, dy).
// ---------------------------------------------------------------------------
__global__ __launch_bounds__(256) void k_bilateral(const float* __restrict__ sigma)
{
    int wid  = (blockIdx.x << 3) + (threadIdx.x >> 5);
    int lane = threadIdx.x & 31;
    int gpix = wid / 7;
    int dyi  = wid - gpix*7;
    int dy   = dyi - 3;

    int p  = (gpix << 5) + lane;
    int b  = p / HWP, pp = p % HWP, yy = pp / WW, xx = pp % WW;
    int ny = yy + dy;
    bool rowok = ((unsigned)ny < HH);
    int nrow = (rowok ? ny : yy) * WW;

    const float* base = g_px_cm + (size_t)b * (CC*HWP);

    int off[7]; unsigned okm = 0;
    #pragma unroll
    for (int i = 0; i < 7; i++) {
        int nx = xx + i - 3;
        bool o = rowok & ((unsigned)nx < WW);
        okm |= (o ? 1u : 0u) << i;
        off[i] = nrow + (o ? nx : xx);
    }

    float acc[7] = {0.f,0.f,0.f,0.f,0.f,0.f,0.f};
    #pragma unroll 4
    for (int c = 0; c < CC; c++) {
        const float* rc = base + c*HWP;
        float cv = rc[pp];
        #pragma unroll
        for (int i = 0; i < 7; i++) acc[i] += cv * rc[off[i]];
    }

    float nc = g_nrm[p];
    float sg = *sigma;
    float is2 = 0.5f / (sg*sg);
    float* outp = &g_comb[p*N2 + dyi*7];
    const float* nrmb = &g_nrm[b*HWP];
    #pragma unroll
    for (int i = 0; i < 7; i++) {
        float res = 0.f;
        if ((okm >> i) & 1u) {
            float d2 = fmaxf(nrmb[off[i]] + nc - 2.f*acc[i], 0.f);
            float fdx = (float)(i - 3);
            res = __expf(-d2*(1.f/128.f) - ((float)(dy*dy) + fdx*fdx)*is2);
        }
        outp[i] = res;
    }
}

// ---------------------------------------------------------------------------
// K3a: fixup: conv49x113 -> LN(49) -> SiLU -> conv49x49; gate + normalize.
// 2 px/warp, f32x2. smem 56960B (4 blk/SM), grid NPIX/16.
// ---------------------------------------------------------------------------
__global__ __launch_bounds__(256, 4) void k_fixup(
    const float* __restrict__ w1, const float* __restrict__ b1,
    const float* __restrict__ g,  const float* __restrict__ be,
    const float* __restrict__ w2, const float* __restrict__ b2)
{
    extern __shared__ float sm[];
    float2* W1v = (float2*)sm;               // [113][32] f2, zero-padded o>=49
    float2* W2v = (float2*)(sm + 7232);      // [49][32] f2
    float*  b1p = sm + 10368;
    float*  gp  = sm + 10432;
    float*  bep = sm + 10496;
    float*  b2p = sm + 10560;
    float*  xs  = sm + 10624;                // [8 warps][113][4] dup
    int tid = threadIdx.x, lane = tid & 31, w = tid >> 5;

    for (int i = tid; i < 113*32; i += 256) {
        int j = i >> 5, l = i & 31;
        float a = (l < N2)    ? w1[l*113 + j]      : 0.f;
        float c = (l+32 < N2) ? w1[(l+32)*113 + j] : 0.f;
        W1v[i] = make_float2(a, c);
    }
    for (int i = tid; i < 49*32; i += 256) {
        int j = i >> 5, l = i & 31;
        float a = (l < N2)    ? w2[l*49 + j]      : 0.f;
        float c = (l+32 < N2) ? w2[(l+32)*49 + j] : 0.f;
        W2v[i] = make_float2(a, c);
    }
    if (tid < 64) {
        b1p[tid] = (tid < N2) ? b1[tid] : 0.f;
        gp[tid]  = (tid < N2) ? g[tid]  : 0.f;
        bep[tid] = (tid < N2) ? be[tid] : 0.f;
        b2p[tid] = (tid < N2) ? b2[tid] : 0.f;
    }

    const bool has2 = (lane + 32) < N2;  // lane < 17
    int pbase = blockIdx.x * 16 + w * 2;
    float* xw = xs + w * 452;

    for (int j = lane; j < 113; j += 32) {
        float v0 = (j < N2) ? g_comb[pbase*N2 + j]     : g_sem_t[pbase*CC + (j - N2)];
        float v1 = (j < N2) ? g_comb[(pbase+1)*N2 + j] : g_sem_t[(pbase+1)*CC + (j - N2)];
        *(float4*)&xw[j*4] = make_float4(v0, v0, v1, v1);
    }
    __syncthreads();

    u64 acc0 = pk2(b1p[lane], b1p[lane+32]);
    u64 acc1 = acc0;
    #pragma unroll 4
    for (int j = 0; j < 113; j++) {
        u64 a = *(const u64*)&W1v[j*32 + lane];
        ulonglong2 xp = *(const ulonglong2*)(xw + j*4);
        fma2(acc0, a, xp.x);
        fma2(acc1, a, xp.y);
    }

    // LN(49) + SiLU per pixel, dup writeback (rows 0..48 only)
    {
        float2 yA = unpk(acc0), yB = unpk(acc1);
        float h0A, h1A, h0B, h1B;
        {
            float s = yA.x + (has2 ? yA.y : 0.f);
            float t = yA.x*yA.x + (has2 ? yA.y*yA.y : 0.f);
            #pragma unroll
            for (int o = 16; o; o >>= 1) {
                s += __shfl_xor_sync(0xffffffffu, s, o);
                t += __shfl_xor_sync(0xffffffffu, t, o);
            }
            float mean = s * (1.f/49.f);
            float rstd = rsqrtf(t * (1.f/49.f) - mean*mean + 1e-6f);
            float a0 = gp[lane]    * (yA.x-mean) * rstd + bep[lane];
            float a1 = gp[lane+32] * (yA.y-mean) * rstd + bep[lane+32];
            h0A = a0 / (1.f + __expf(-a0));
            h1A = a1 / (1.f + __expf(-a1));
        }
        {
            float s = yB.x + (has2 ? yB.y : 0.f);
            float t = yB.x*yB.x + (has2 ? yB.y*yB.y : 0.f);
            #pragma unroll
            for (int o = 16; o; o >>= 1) {
                s += __shfl_xor_sync(0xffffffffu, s, o);
                t += __shfl_xor_sync(0xffffffffu, t, o);
            }
            float mean = s * (1.f/49.f);
            float rstd = rsqrtf(t * (1.f/49.f) - mean*mean + 1e-6f);
            float a0 = gp[lane]    * (yB.x-mean) * rstd + bep[lane];
            float a1 = gp[lane+32] * (yB.y-mean) * rstd + bep[lane+32];
            h0B = a0 / (1.f + __expf(-a0));
            h1B = a1 / (1.f + __expf(-a1));
        }
        __syncwarp();
        *(float4*)&xw[lane*4] = make_float4(h0A, h0A, h0B, h0B);
        if (has2) *(float4*)&xw[(lane+32)*4] = make_float4(h1A, h1A, h1B, h1B);
        __syncwarp();
    }

    acc0 = pk2(b2p[lane], b2p[lane+32]);
    acc1 = acc0;
    #pragma unroll 4
    for (int j = 0; j < 49; j++) {
        u64 a = *(const u64*)&W2v[j*32 + lane];
        ulonglong2 xp = *(const ulonglong2*)(xw + j*4);
        fma2(acc0, a, xp.x);
        fma2(acc1, a, xp.y);
    }

    {
        float2 yA = unpk(acc0), yB = unpk(acc1);
        // pixel 0
        {
            float cb0 = g_comb[pbase*N2 + lane];
            float cb1 = has2 ? g_comb[pbase*N2 + lane + 32] : 0.f;
            float wv0 = cb0 * (1.f + 1.f/(1.f + __expf(-yA.x)));
            float wv1 = cb1 * (1.f + 1.f/(1.f + __expf(-yA.y)));
            if (!has2) wv1 = 0.f;
            float ss = wv0 + wv1;
            #pragma unroll
            for (int o = 16; o; o >>= 1) ss += __shfl_xor_sync(0xffffffffu, ss, o);
            float inv = 1.f / (ss + 1e-7f);
            g_comb[pbase*N2 + lane] = wv0 * inv;
            if (has2) g_comb[pbase*N2 + lane + 32] = wv1 * inv;
        }
        // pixel 1
        {
            float cb0 = g_comb[(pbase+1)*N2 + lane];
            float cb1 = has2 ? g_comb[(pbase+1)*N2 + lane + 32] : 0.f;
            float wv0 = cb0 * (1.f + 1.f/(1.f + __expf(-yB.x)));
            float wv1 = cb1 * (1.f + 1.f/(1.f + __expf(-yB.y)));
            if (!has2) wv1 = 0.f;
            float ss = wv0 + wv1;
            #pragma unroll
            for (int o = 16; o; o >>= 1) ss += __shfl_xor_sync(0xffffffffu, ss, o);
            float inv = 1.f / (ss + 1e-7f);
            g_comb[(pbase+1)*N2 + lane] = wv0 * inv;
            if (has2) g_comb[(pbase+1)*N2 + lane + 32] = wv1 * inv;
        }
    }
}

// ---------------------------------------------------------------------------
// K3b: weighted neighborhood reduction + output_proj (conv -> LN -> conv)
// 2 px/warp, f32x2. Gather predicate-free (clamped addr, comb==0 for OOB).
// ---------------------------------------------------------------------------
__global__ __launch_bounds__(256, 5) void k_output(
    const float* __restrict__ w1, const float* __restrict__ b1,
    const float* __restrict__ g,  const float* __restrict__ be,
    const float* __restrict__ w2, const float* __restrict__ b2,
    float* __restrict__ out)
{
    extern __shared__ float sm[];
    float2* W1v = (float2*)sm;              // [64][32] f2
    float2* W2v = (float2*)(sm + 4096);
    float*  b1s = sm + 8192;
    float*  gs  = sm + 8256;
    float*  bes = sm + 8320;
    float*  b2s = sm + 8384;
    float*  wsb = sm + 8448;                // [8][52]
    float*  os  = sm + 8864;                // [8 warps][64][4] dup
    int tid = threadIdx.x, lane = tid & 31, w = tid >> 5;

    for (int i = tid; i < 2048; i += 256) {
        int c = i >> 5, l = i & 31;
        W1v[i] = make_float2(w1[l*64 + c], w1[(l+32)*64 + c]);
        W2v[i] = make_float2(w2[l*64 + c], w2[(l+32)*64 + c]);
    }
    if (tid < 64) { b1s[tid]=b1[tid]; gs[tid]=g[tid]; bes[tid]=be[tid]; b2s[tid]=b2[tid]; }
    __syncthreads();

    int pbase = blockIdx.x * 16 + w * 2;
    float* ow   = os  + w * 256;
    float* wrow = wsb + w * 52;

    // Gather (lane owns channels 2*lane, 2*lane+1), predicate-free
    {
        float a0[2], a1[2];
        #pragma unroll
        for (int q = 0; q < 2; q++) {
            int p = pbase + q;
            int b = p / HWP, pp = p % HWP, yy = pp / WW, xx = pp % WW;

            for (int n = lane; n < N2; n += 32) wrow[n] = g_comb[p*N2 + n];
            __syncwarp();

            float s0 = 0.f, s1 = 0.f;
            int n = 0;
            #pragma unroll
            for (int dy = -3; dy <= 3; dy++) {
                int ny = min(max(yy + dy, 0), HH-1);
                const float* rbase = &g_spa_t[(b*HWP + ny*WW)*CC + lane*2];
                #pragma unroll
                for (int dx = -3; dx <= 3; dx++, n++) {
                    int nx = min(max(xx + dx, 0), WW-1);
                    float wv = wrow[n];                  // 0 for OOB neighbors
                    float2 sv = *(const float2*)(rbase + nx*CC);
                    s0 += sv.x * wv;
                    s1 += sv.y * wv;
                }
            }
            a0[q] = s0; a1[q] = s1;
            __syncwarp();
        }
        *(float4*)&ow[(lane*2)*4]   = make_float4(a0[0], a0[0], a0[1], a0[1]);
        *(float4*)&ow[(lane*2+1)*4] = make_float4(a1[0], a1[0], a1[1], a1[1]);
        __syncwarp();
    }

    u64 acc0 = pk2(b1s[lane], b1s[lane+32]);
    u64 acc1 = acc0;
    #pragma unroll 8
    for (int c = 0; c < 64; c++) {
        u64 a = *(const u64*)&W1v[c*32 + lane];
        ulonglong2 xp = *(const ulonglong2*)(ow + c*4);
        fma2(acc0, a, xp.x);
        fma2(acc1, a, xp.y);
    }

    {
        float2 yA = unpk(acc0), yB = unpk(acc1);
        float h0A, h1A, h0B, h1B;
        {
            float s = yA.x + yA.y, t = yA.x*yA.x + yA.y*yA.y;
            #pragma unroll
            for (int o = 16; o; o >>= 1) {
                s += __shfl_xor_sync(0xffffffffu, s, o);
                t += __shfl_xor_sync(0xffffffffu, t, o);
            }
            float mean = s * (1.f/64.f);
            float rstd = rsqrtf(t * (1.f/64.f) - mean*mean + 1e-6f);
            h0A = gs[lane]    * (yA.x-mean) * rstd + bes[lane];
            h1A = gs[lane+32] * (yA.y-mean) * rstd + bes[lane+32];
        }
        {
            float s = yB.x + yB.y, t = yB.x*yB.x + yB.y*yB.y;
            #pragma unroll
            for (int o = 16; o; o >>= 1) {
                s += __shfl_xor_sync(0xffffffffu, s, o);
                t += __shfl_xor_sync(0xffffffffu, t, o);
            }
            float mean = s * (1.f/64.f);
            float rstd = rsqrtf(t * (1.f/64.f) - mean*mean + 1e-6f);
            h0B = gs[lane]    * (yB.x-mean) * rstd + bes[lane];
            h1B = gs[lane+32] * (yB.y-mean) * rstd + bes[lane+32];
        }
        __syncwarp();
        *(float4*)&ow[lane*4]      = make_float4(h0A, h0A, h0B, h0B);
        *(float4*)&ow[(lane+32)*4] = make_float4(h1A, h1A, h1B, h1B);
        __syncwarp();
    }

    acc0 = pk2(b2s[lane], b2s[lane+32]);
    acc1 = acc0;
    #pragma unroll 8
    for (int c = 0; c < 64; c++) {
        u64 a = *(const u64*)&W2v[c*32 + lane];
        ulonglong2 xp = *(const ulonglong2*)(ow + c*4);
        fma2(acc0, a, xp.x);
        fma2(acc1, a, xp.y);
    }

    {
        float2 yA = unpk(acc0), yB = unpk(acc1);
        int b = pbase / HWP, pp = pbase % HWP;
        *(float2*)&out[(b*CC + lane)*HWP + pp]      = make_float2(yA.x, yB.x);
        *(float2*)&out[(b*CC + lane + 32)*HWP + pp] = make_float2(yA.y, yB.y);
    }
}

// ---------------------------------------------------------------------------
extern "C" void kernel_launch(void* const* d_in, const int* in_sizes, int n_in,
                              void* d_out, int out_size)
{
    const float* spa = (const float*)d_in[0];
    const float* sem = (const float*)d_in[1];

    static bool attr_set = false;
    if (!attr_set) {
        cudaFuncSetAttribute(k_range,  cudaFuncAttributeMaxDynamicSharedMemorySize, 41984);
        cudaFuncSetAttribute(k_fixup,  cudaFuncAttributeMaxDynamicSharedMemorySize, 56960);
        cudaFuncSetAttribute(k_output, cudaFuncAttributeMaxDynamicSharedMemorySize, 43648);
        attr_set = true;
    }

    dim3 tg(HWP/32, CC/32, BB), tb(32, 8);
    k_transpose2<<<tg, tb>>>(sem, spa);

    k_range<<<NPIX/16, 256, 41984>>>((const float*)d_in[2], (const float*)d_in[3],
                                     (const float*)d_in[4], (const float*)d_in[5],
                                     (const float*)d_in[6], (const float*)d_in[7]);

    // warps = (NPIX/32) * 7 = 5488 ; 8 warps/block -> 686 blocks
    k_bilateral<<<686, 256>>>((const float*)d_in[20]);

    k_fixup<<<NPIX/16, 256, 56960>>>((const float*)d_in[8],  (const float*)d_in[9],
                                     (const float*)d_in[10], (const float*)d_in[11],
                                     (const float*)d_in[12], (const float*)d_in[13]);

    k_output<<<NPIX/16, 256, 43648>>>((const float*)d_in[14], (const float*)d_in[15],
                                      (const float*)d_in[16], (const float*)d_in[17],
                                      (const float*)d_in[18], (const float*)d_in[19],
                                      (float*)d_out);
}

// round 9
// speedup vs baseline: 1.5672x; 1.5672x over previous
#include <cuda_runtime.h>

// ---------------------------------------------------------------------------
// SpatialRangeAttention — GB300 sm_103a
// ---------------------------------------------------------------------------

#define BB   2
#define CC   64
#define HH   112
#define WW   112
#define HWP  (HH*WW)      // 12544
#define NPIX (BB*HWP)     // 25088
#define N2   49

// Scratch
__device__ float g_sem_t[NPIX*CC];   // semantic transposed [pix][c]
__device__ float g_spa_t[NPIX*CC];   // spatial  transposed [pix][c]
__device__ float g_px_cm[NPIX*CC];   // range-projected, CHANNEL-major [b][c][hw]
__device__ float g_nrm[NPIX];        // per-pixel ||px||^2
__device__ float g_comb[NPIX*N2];    // bilateral / final weights [pix][n]

// 32-FMA block: weight pair a=(w[o],w[o+32]) times 16 pixel x-values
#define ACC32(a, xA, xB, xC, xD)                      \
    y0[0] += a.x*xA.x;  y1[0] += a.y*xA.x;            \
    y0[1] += a.x*xA.y;  y1[1] += a.y*xA.y;            \
    y0[2] += a.x*xA.z;  y1[2] += a.y*xA.z;            \
    y0[3] += a.x*xA.w;  y1[3] += a.y*xA.w;            \
    y0[4] += a.x*xB.x;  y1[4] += a.y*xB.x;            \
    y0[5] += a.x*xB.y;  y1[5] += a.y*xB.y;            \
    y0[6] += a.x*xB.z;  y1[6] += a.y*xB.z;            \
    y0[7] += a.x*xB.w;  y1[7] += a.y*xB.w;            \
    y0[8] += a.x*xC.x;  y1[8] += a.y*xC.x;            \
    y0[9] += a.x*xC.y;  y1[9] += a.y*xC.y;            \
    y0[10]+= a.x*xC.z;  y1[10]+= a.y*xC.z;            \
    y0[11]+= a.x*xC.w;  y1[11]+= a.y*xC.w;            \
    y0[12]+= a.x*xD.x;  y1[12]+= a.y*xD.x;            \
    y0[13]+= a.x*xD.y;  y1[13]+= a.y*xD.y;            \
    y0[14]+= a.x*xD.z;  y1[14]+= a.y*xD.z;            \
    y0[15]+= a.x*xD.w;  y1[15]+= a.y*xD.w;

// ---------------------------------------------------------------------------
// K0: transpose both inputs [B,C,HW] -> [B*HW, C]
// ---------------------------------------------------------------------------
__global__ __launch_bounds__(256) void k_transpose2(
    const float* __restrict__ sem, const float* __restrict__ spa)
{
    __shared__ float t1[32][33];
    __shared__ float t2[32][33];
    int b  = blockIdx.z;
    int c0 = blockIdx.y * 32;
    int p0 = blockIdx.x * 32;
    int tx = threadIdx.x, ty = threadIdx.y;
    #pragma unroll
    for (int i = ty; i < 32; i += 8) {
        int c = c0 + i, p = p0 + tx;
        t1[i][tx] = sem[(b*CC + c)*HWP + p];
        t2[i][tx] = spa[(b*CC + c)*HWP + p];
    }
    __syncthreads();
    #pragma unroll
    for (int i = ty; i < 32; i += 8) {
        int p = p0 + i, c = c0 + tx;
        g_sem_t[(b*HWP + p)*CC + c] = t1[tx][i];
        g_spa_t[(b*HWP + p)*CC + c] = t2[tx][i];
    }
}

// ---------------------------------------------------------------------------
// K1: range_proj: conv -> LN -> SiLU -> conv. 16 px/warp, 32 accumulators.
// 128 threads (4 warps/block). Outputs channel-major px + norms.
// smem = 50176B -> 4 blocks/SM. grid NPIX/64 = 392.
// ---------------------------------------------------------------------------
__global__ __launch_bounds__(128, 4) void k_range(
    const float* __restrict__ w1, const float* __restrict__ b1,
    const float* __restrict__ g,  const float* __restrict__ be,
    const float* __restrict__ w2, const float* __restrict__ b2)
{
    extern __shared__ float sm[];
    float2* W1v = (float2*)sm;              // [64][32] f2 (pair = out o,o+32)
    float2* W2v = (float2*)(sm + 4096);
    float*  b1s = sm + 8192;
    float*  gs  = sm + 8256;
    float*  bes = sm + 8320;
    float*  b2s = sm + 8384;
    float*  xs  = sm + 8448;                // [4 warps][64 rows][16 px]
    int tid = threadIdx.x, lane = tid & 31, w = tid >> 5;

    for (int i = tid; i < 2048; i += 128) {
        int c = i >> 5, l = i & 31;
        W1v[i] = make_float2(w1[l*64 + c], w1[(l+32)*64 + c]);
        W2v[i] = make_float2(w2[l*64 + c], w2[(l+32)*64 + c]);
    }
    if (tid < 64) { b1s[tid]=b1[tid]; gs[tid]=g[tid]; bes[tid]=be[tid]; b2s[tid]=b2[tid]; }

    int pbase = blockIdx.x * 64 + w * 16;
    float* xw = xs + w * 1024;

    // stage 16 pixels transposed: lane q owns pixel q; halves split channel range
    {
        int q = lane & 15, half = lane >> 4;
        const float* semp = g_sem_t + (pbase + q)*CC;
        int c0 = half * 32;
        for (int i = 0; i < 32; i++) {
            int ii = half ? (i ^ 1) : i;      // parity stagger -> conflict-free
            int c = c0 + ii;
            xw[c*16 + q] = semp[c];
        }
    }
    __syncthreads();

    float y0[16], y1[16];
    #pragma unroll
    for (int q = 0; q < 16; q++) { y0[q] = b1s[lane]; y1[q] = b1s[lane+32]; }

    #pragma unroll 2
    for (int c = 0; c < 64; c++) {
        float2 a = W1v[c*32 + lane];
        float4 xA = *(const float4*)(xw + c*16);
        float4 xB = *(const float4*)(xw + c*16 + 4);
        float4 xC = *(const float4*)(xw + c*16 + 8);
        float4 xD = *(const float4*)(xw + c*16 + 12);
        ACC32(a, xA, xB, xC, xD)
    }

    // LN + SiLU per pixel
    {
        float h0[16], h1[16];
        #pragma unroll
        for (int q = 0; q < 16; q++) {
            float s = y0[q] + y1[q];
            float t = y0[q]*y0[q] + y1[q]*y1[q];
            #pragma unroll
            for (int o = 16; o; o >>= 1) {
                s += __shfl_xor_sync(0xffffffffu, s, o);
                t += __shfl_xor_sync(0xffffffffu, t, o);
            }
            float mean = s * (1.f/64.f);
            float rstd = rsqrtf(t * (1.f/64.f) - mean*mean + 1e-6f);
            float a0 = gs[lane]    * (y0[q]-mean) * rstd + bes[lane];
            float a1 = gs[lane+32] * (y1[q]-mean) * rstd + bes[lane+32];
            h0[q] = a0 / (1.f + __expf(-a0));
            h1[q] = a1 / (1.f + __expf(-a1));
        }
        __syncwarp();
        *(float4*)&xw[lane*16]          = make_float4(h0[0],h0[1],h0[2],h0[3]);
        *(float4*)&xw[lane*16 + 4]      = make_float4(h0[4],h0[5],h0[6],h0[7]);
        *(float4*)&xw[lane*16 + 8]      = make_float4(h0[8],h0[9],h0[10],h0[11]);
        *(float4*)&xw[lane*16 + 12]     = make_float4(h0[12],h0[13],h0[14],h0[15]);
        *(float4*)&xw[(lane+32)*16]     = make_float4(h1[0],h1[1],h1[2],h1[3]);
        *(float4*)&xw[(lane+32)*16 + 4] = make_float4(h1[4],h1[5],h1[6],h1[7]);
        *(float4*)&xw[(lane+32)*16 + 8] = make_float4(h1[8],h1[9],h1[10],h1[11]);
        *(float4*)&xw[(lane+32)*16 +12] = make_float4(h1[12],h1[13],h1[14],h1[15]);
        __syncwarp();
    }

    #pragma unroll
    for (int q = 0; q < 16; q++) { y0[q] = b2s[lane]; y1[q] = b2s[lane+32]; }
    #pragma unroll 2
    for (int c = 0; c < 64; c++) {
        float2 a = W2v[c*32 + lane];
        float4 xA = *(const float4*)(xw + c*16);
        float4 xB = *(const float4*)(xw + c*16 + 4);
        float4 xC = *(const float4*)(xw + c*16 + 8);
        float4 xD = *(const float4*)(xw + c*16 + 12);
        ACC32(a, xA, xB, xC, xD)
    }

    // norms per pixel
    #pragma unroll
    for (int q = 0; q < 16; q++) {
        float t = y0[q]*y0[q] + y1[q]*y1[q];
        #pragma unroll
        for (int o = 16; o; o >>= 1) t += __shfl_xor_sync(0xffffffffu, t, o);
        if (lane == 0) g_nrm[pbase + q] = t;
    }
    // channel-major stores: 16 consecutive pixels -> 4x STG.128 per half
    {
        int b = pbase / HWP, pp = pbase % HWP;
        float* d0 = &g_px_cm[(size_t)(b*CC + lane)*HWP + pp];
        *(float4*)d0        = make_float4(y0[0],y0[1],y0[2],y0[3]);
        *(float4*)(d0 + 4)  = make_float4(y0[4],y0[5],y0[6],y0[7]);
        *(float4*)(d0 + 8)  = make_float4(y0[8],y0[9],y0[10],y0[11]);
        *(float4*)(d0 + 12) = make_float4(y0[12],y0[13],y0[14],y0[15]);
        float* d1 = &g_px_cm[(size_t)(b*CC + lane + 32)*HWP + pp];
        *(float4*)d1        = make_float4(y1[0],y1[1],y1[2],y1[3]);
        *(float4*)(d1 + 4)  = make_float4(y1[4],y1[5],y1[6],y1[7]);
        *(float4*)(d1 + 8)  = make_float4(y1[8],y1[9],y1[10],y1[11]);
        *(float4*)(d1 + 12) = make_float4(y1[12],y1[13],y1[14],y1[15]);
    }
}

// ---------------------------------------------------------------------------
// K2: bilateral via dot-form: dist2 = |n|^2+|c|^2-2dot. Warp = (32 pixels, dy).
// ---------------------------------------------------------------------------
__global__ __launch_bounds__(256) void k_bilateral(const float* __restrict__ sigma)
{
    int wid  = (blockIdx.x << 3) + (threadIdx.x >> 5);
    int lane = threadIdx.x & 31;
    int gpix = wid / 7;
    int dyi  = wid - gpix*7;
    int dy   = dyi - 3;

    int p  = (gpix << 5) + lane;
    int b  = p / HWP, pp = p % HWP, yy = pp / WW, xx = pp % WW;
    int ny = yy + dy;
    bool rowok = ((unsigned)ny < HH);
    int nrow = (rowok ? ny : yy) * WW;

    const float* base = g_px_cm + (size_t)b * (CC*HWP);

    int off[7]; unsigned okm = 0;
    #pragma unroll
    for (int i = 0; i < 7; i++) {
        int nx = xx + i - 3;
        bool o = rowok & ((unsigned)nx < WW);
        okm |= (o ? 1u : 0u) << i;
        off[i] = nrow + (o ? nx : xx);
    }

    float acc[7] = {0.f,0.f,0.f,0.f,0.f,0.f,0.f};
    #pragma unroll 4
    for (int c = 0; c < CC; c++) {
        const float* rc = base + c*HWP;
        float cv = rc[pp];
        #pragma unroll
        for (int i = 0; i < 7; i++) acc[i] += cv * rc[off[i]];
    }

    float nc = g_nrm[p];
    float sg = *sigma;
    float is2 = 0.5f / (sg*sg);
    float* outp = &g_comb[p*N2 + dyi*7];
    const float* nrmb = &g_nrm[b*HWP];
    #pragma unroll
    for (int i = 0; i < 7; i++) {
        float res = 0.f;
        if ((okm >> i) & 1u) {
            float d2 = fmaxf(nrmb[off[i]] + nc - 2.f*acc[i], 0.f);
            float fdx = (float)(i - 3);
            res = __expf(-d2*(1.f/128.f) - ((float)(dy*dy) + fdx*fdx)*is2);
        }
        outp[i] = res;
    }
}

// ---------------------------------------------------------------------------
// K3a: fixup: conv49x113 -> LN(49) -> SiLU -> conv49x49; gate + normalize.
// 16 px/warp, 32 accumulators, 128 threads. smem 71424B -> 3 blocks/SM.
// ---------------------------------------------------------------------------
__global__ __launch_bounds__(128, 3) void k_fixup(
    const float* __restrict__ w1, const float* __restrict__ b1,
    const float* __restrict__ g,  const float* __restrict__ be,
    const float* __restrict__ w2, const float* __restrict__ b2)
{
    extern __shared__ float sm[];
    float2* W1v = (float2*)sm;               // [113][32] f2, zero-padded o>=49
    float2* W2v = (float2*)(sm + 7232);      // [49][32] f2
    float*  b1p = sm + 10368;
    float*  gp  = sm + 10432;
    float*  bep = sm + 10496;
    float*  b2p = sm + 10560;
    float*  xs  = sm + 10624;                // [4 warps][113][16]
    int tid = threadIdx.x, lane = tid & 31, w = tid >> 5;

    for (int i = tid; i < 113*32; i += 128) {
        int j = i >> 5, l = i & 31;
        float a = (l < N2)    ? w1[l*113 + j]      : 0.f;
        float c = (l+32 < N2) ? w1[(l+32)*113 + j] : 0.f;
        W1v[i] = make_float2(a, c);
    }
    for (int i = tid; i < 49*32; i += 128) {
        int j = i >> 5, l = i & 31;
        float a = (l < N2)    ? w2[l*49 + j]      : 0.f;
        float c = (l+32 < N2) ? w2[(l+32)*49 + j] : 0.f;
        W2v[i] = make_float2(a, c);
    }
    if (tid < 64) {
        b1p[tid] = (tid < N2) ? b1[tid] : 0.f;
        gp[tid]  = (tid < N2) ? g[tid]  : 0.f;
        bep[tid] = (tid < N2) ? be[tid] : 0.f;
        b2p[tid] = (tid < N2) ? b2[tid] : 0.f;
    }

    const bool has2 = (lane + 32) < N2;  // lane < 17
    int pbase = blockIdx.x * 64 + w * 16;
    float* xw = xs + w * 1808;

    // stage transposed: lane q owns pixel q; halves split j range (divergent
    // branches serialize the halves -> each half's 16 stores hit 16 distinct banks)
    {
        int q = lane & 15, half = lane >> 4;
        int p = pbase + q;
        const float* combp = g_comb + p*N2;
        const float* semp  = g_sem_t + p*CC;
        if (half == 0) {
            for (int j = 0; j < 57; j++) {
                float v = (j < N2) ? combp[j] : semp[j - N2];
                xw[j*16 + q] = v;
            }
        } else {
            for (int j = 57; j < 113; j++)
                xw[j*16 + q] = semp[j - N2];   // j >= 57 is always sem
        }
    }
    __syncthreads();

    float y0[16], y1[16];
    #pragma unroll
    for (int q = 0; q < 16; q++) { y0[q] = b1p[lane]; y1[q] = b1p[lane+32]; }

    #pragma unroll 2
    for (int j = 0; j < 113; j++) {
        float2 a = W1v[j*32 + lane];
        float4 xA = *(const float4*)(xw + j*16);
        float4 xB = *(const float4*)(xw + j*16 + 4);
        float4 xC = *(const float4*)(xw + j*16 + 8);
        float4 xD = *(const float4*)(xw + j*16 + 12);
        ACC32(a, xA, xB, xC, xD)
    }

    // LN(49) + SiLU per pixel
    {
        float h0[16], h1[16];
        #pragma unroll
        for (int q = 0; q < 16; q++) {
            float s = y0[q] + (has2 ? y1[q] : 0.f);
            float t = y0[q]*y0[q] + (has2 ? y1[q]*y1[q] : 0.f);
            #pragma unroll
            for (int o = 16; o; o >>= 1) {
                s += __shfl_xor_sync(0xffffffffu, s, o);
                t += __shfl_xor_sync(0xffffffffu, t, o);
            }
            float mean = s * (1.f/49.f);
            float rstd = rsqrtf(t * (1.f/49.f) - mean*mean + 1e-6f);
            float a0 = gp[lane]    * (y0[q]-mean) * rstd + bep[lane];
            float a1 = gp[lane+32] * (y1[q]-mean) * rstd + bep[lane+32];
            h0[q] = a0 / (1.f + __expf(-a0));
            h1[q] = a1 / (1.f + __expf(-a1));
        }
        __syncwarp();
        *(float4*)&xw[lane*16]      = make_float4(h0[0],h0[1],h0[2],h0[3]);
        *(float4*)&xw[lane*16 + 4]  = make_float4(h0[4],h0[5],h0[6],h0[7]);
        *(float4*)&xw[lane*16 + 8]  = make_float4(h0[8],h0[9],h0[10],h0[11]);
        *(float4*)&xw[lane*16 + 12] = make_float4(h0[12],h0[13],h0[14],h0[15]);
        if (has2) {
            *(float4*)&xw[(lane+32)*16]      = make_float4(h1[0],h1[1],h1[2],h1[3]);
            *(float4*)&xw[(lane+32)*16 + 4]  = make_float4(h1[4],h1[5],h1[6],h1[7]);
            *(float4*)&xw[(lane+32)*16 + 8]  = make_float4(h1[8],h1[9],h1[10],h1[11]);
            *(float4*)&xw[(lane+32)*16 +12]  = make_float4(h1[12],h1[13],h1[14],h1[15]);
        }
        __syncwarp();
    }

    #pragma unroll
    for (int q = 0; q < 16; q++) { y0[q] = b2p[lane]; y1[q] = b2p[lane+32]; }
    #pragma unroll 2
    for (int j = 0; j < 49; j++) {
        float2 a = W2v[j*32 + lane];
        float4 xA = *(const float4*)(xw + j*16);
        float4 xB = *(const float4*)(xw + j*16 + 4);
        float4 xC = *(const float4*)(xw + j*16 + 8);
        float4 xD = *(const float4*)(xw + j*16 + 12);
        ACC32(a, xA, xB, xC, xD)
    }

    #pragma unroll
    for (int q = 0; q < 16; q++) {
        int p = pbase + q;
        float cb0 = g_comb[p*N2 + lane];
        float cb1 = has2 ? g_comb[p*N2 + lane + 32] : 0.f;
        float wv0 = cb0 * (1.f + 1.f/(1.f + __expf(-y0[q])));
        float wv1 = has2 ? cb1 * (1.f + 1.f/(1.f + __expf(-y1[q]))) : 0.f;
        float ss = wv0 + wv1;
        #pragma unroll
        for (int o = 16; o; o >>= 1) ss += __shfl_xor_sync(0xffffffffu, ss, o);
        float inv = 1.f / (ss + 1e-7f);
        g_comb[p*N2 + lane] = wv0 * inv;
        if (has2) g_comb[p*N2 + lane + 32] = wv1 * inv;
    }
}

// ---------------------------------------------------------------------------
// K3b: weighted neighborhood reduction + output_proj (conv -> LN -> conv)
// 8 px/warp (R6 structure); gather clamped predicate-free.
// ---------------------------------------------------------------------------
__global__ __launch_bounds__(256, 3) void k_output(
    const float* __restrict__ w1, const float* __restrict__ b1,
    const float* __restrict__ g,  const float* __restrict__ be,
    const float* __restrict__ w2, const float* __restrict__ b2,
    float* __restrict__ out)
{
    extern __shared__ float sm[];
    float2* W1v = (float2*)sm;              // [64][32] f2
    float2* W2v = (float2*)(sm + 4096);
    float*  b1s = sm + 8192;
    float*  gs  = sm + 8256;
    float*  bes = sm + 8320;
    float*  b2s = sm + 8384;
    float*  wsb = sm + 8448;                // [8][52]
    float*  os  = sm + 8864;                // [8][64][8]
    int tid = threadIdx.x, lane = tid & 31, w = tid >> 5;

    for (int i = tid; i < 2048; i += 256) {
        int c = i >> 5, l = i & 31;
        W1v[i] = make_float2(w1[l*64 + c], w1[(l+32)*64 + c]);
        W2v[i] = make_float2(w2[l*64 + c], w2[(l+32)*64 + c]);
    }
    if (tid < 64) { b1s[tid]=b1[tid]; gs[tid]=g[tid]; bes[tid]=be[tid]; b2s[tid]=b2[tid]; }
    __syncthreads();

    int pbase = blockIdx.x * 64 + w * 8;
    float* ow   = os  + w * 512;
    float* wrow = wsb + w * 52;

    // Gather: lane owns channels (2*lane, 2*lane+1); clamped, predicate-free
    {
        float a0[8], a1[8];
        for (int q = 0; q < 8; q++) {
            int p = pbase + q;
            int b = p / HWP, pp = p % HWP, yy = pp / WW, xx = pp % WW;

            for (int n = lane; n < N2; n += 32) wrow[n] = g_comb[p*N2 + n];
            __syncwarp();

            float s0 = 0.f, s1 = 0.f;
            int n = 0;
            #pragma unroll
            for (int dy = -3; dy <= 3; dy++) {
                int ny = min(max(yy + dy, 0), HH-1);
                const float* rbase = &g_spa_t[(b*HWP + ny*WW)*CC + lane*2];
                #pragma unroll
                for (int dx = -3; dx <= 3; dx++, n++) {
                    int nx = min(max(xx + dx, 0), WW-1);
                    float wv = wrow[n];                  // 0 for OOB neighbors
                    float2 sv = *(const float2*)(rbase + nx*CC);
                    s0 += sv.x * wv;
                    s1 += sv.y * wv;
                }
            }
            a0[q] = s0; a1[q] = s1;
            __syncwarp();
        }
        *(float4*)&ow[(lane*2)*8]       = make_float4(a0[0],a0[1],a0[2],a0[3]);
        *(float4*)&ow[(lane*2)*8 + 4]   = make_float4(a0[4],a0[5],a0[6],a0[7]);
        *(float4*)&ow[(lane*2+1)*8]     = make_float4(a1[0],a1[1],a1[2],a1[3]);
        *(float4*)&ow[(lane*2+1)*8 + 4] = make_float4(a1[4],a1[5],a1[6],a1[7]);
        __syncwarp();
    }

    float y0[8], y1[8];
    #pragma unroll
    for (int q = 0; q < 8; q++) { y0[q] = b1s[lane]; y1[q] = b1s[lane+32]; }
    #pragma unroll 4
    for (int c = 0; c < 64; c++) {
        float2 a = W1v[c*32 + lane];
        float4 xa = *(const float4*)(ow + c*8);
        float4 xb = *(const float4*)(ow + c*8 + 4);
        y0[0]+=a.x*xa.x; y1[0]+=a.y*xa.x;
        y0[1]+=a.x*xa.y; y1[1]+=a.y*xa.y;
        y0[2]+=a.x*xa.z; y1[2]+=a.y*xa.z;
        y0[3]+=a.x*xa.w; y1[3]+=a.y*xa.w;
        y0[4]+=a.x*xb.x; y1[4]+=a.y*xb.x;
        y0[5]+=a.x*xb.y; y1[5]+=a.y*xb.y;
        y0[6]+=a.x*xb.z; y1[6]+=a.y*xb.z;
        y0[7]+=a.x*xb.w; y1[7]+=a.y*xb.w;
    }

    {
        float h0[8], h1[8];
        #pragma unroll
        for (int q = 0; q < 8; q++) {
            float s = y0[q] + y1[q];
            float t = y0[q]*y0[q] + y1[q]*y1[q];
            #pragma unroll
            for (int o = 16; o; o >>= 1) {
                s += __shfl_xor_sync(0xffffffffu, s, o);
                t += __shfl_xor_sync(0xffffffffu, t, o);
            }
            float mean = s * (1.f/64.f);
            float rstd = rsqrtf(t * (1.f/64.f) - mean*mean + 1e-6f);
            h0[q] = gs[lane]    * (y0[q]-mean) * rstd + bes[lane];
            h1[q] = gs[lane+32] * (y1[q]-mean) * rstd + bes[lane+32];
        }
        __syncwarp();
        *(float4*)&ow[lane*8]          = make_float4(h0[0],h0[1],h0[2],h0[3]);
        *(float4*)&ow[lane*8 + 4]      = make_float4(h0[4],h0[5],h0[6],h0[7]);
        *(float4*)&ow[(lane+32)*8]     = make_float4(h1[0],h1[1],h1[2],h1[3]);
        *(float4*)&ow[(lane+32)*8 + 4] = make_float4(h1[4],h1[5],h1[6],h1[7]);
        __syncwarp();
    }

    #pragma unroll
    for (int q = 0; q < 8; q++) { y0[q] = b2s[lane]; y1[q] = b2s[lane+32]; }
    #pragma unroll 4
    for (int c = 0; c < 64; c++) {
        float2 a = W2v[c*32 + lane];
        float4 xa = *(const float4*)(ow + c*8);
        float4 xb = *(const float4*)(ow + c*8 + 4);
        y0[0]+=a.x*xa.x; y1[0]+=a.y*xa.x;
        y0[1]+=a.x*xa.y; y1[1]+=a.y*xa.y;
        y0[2]+=a.x*xa.z; y1[2]+=a.y*xa.z;
        y0[3]+=a.x*xa.w; y1[3]+=a.y*xa.w;
        y0[4]+=a.x*xb.x; y1[4]+=a.y*xb.x;
        y0[5]+=a.x*xb.y; y1[5]+=a.y*xb.y;
        y0[6]+=a.x*xb.z; y1[6]+=a.y*xb.z;
        y0[7]+=a.x*xb.w; y1[7]+=a.y*xb.w;
    }

    #pragma unroll
    for (int q = 0; q < 8; q++) {
        int p = pbase + q;
        int b = p / HWP, pp = p % HWP;
        out[(b*CC + lane)*HWP + pp]      = y0[q];
        out[(b*CC + lane + 32)*HWP + pp] = y1[q];
    }
}

// ---------------------------------------------------------------------------
extern "C" void kernel_launch(void* const* d_in, const int* in_sizes, int n_in,
                              void* d_out, int out_size)
{
    const float* spa = (const float*)d_in[0];
    const float* sem = (const float*)d_in[1];

    static bool attr_set = false;
    if (!attr_set) {
        cudaFuncSetAttribute(k_range,  cudaFuncAttributeMaxDynamicSharedMemorySize, 50176);
        cudaFuncSetAttribute(k_fixup,  cudaFuncAttributeMaxDynamicSharedMemorySize, 71424);
        cudaFuncSetAttribute(k_output, cudaFuncAttributeMaxDynamicSharedMemorySize, 51840);
        attr_set = true;
    }

    dim3 tg(HWP/32, CC/32, BB), tb(32, 8);
    k_transpose2<<<tg, tb>>>(sem, spa);

    k_range<<<NPIX/64, 128, 50176>>>((const float*)d_in[2], (const float*)d_in[3],
                                     (const float*)d_in[4], (const float*)d_in[5],
                                     (const float*)d_in[6], (const float*)d_in[7]);

    // warps = (NPIX/32) * 7 = 5488 ; 8 warps/block -> 686 blocks
    k_bilateral<<<686, 256>>>((const float*)d_in[20]);

    k_fixup<<<NPIX/64, 128, 71424>>>((const float*)d_in[8],  (const float*)d_in[9],
                                     (const float*)d_in[10], (const float*)d_in[11],
                                     (const float*)d_in[12], (const float*)d_in[13]);

    k_output<<<NPIX/64, 256, 51840>>>((const float*)d_in[14], (const float*)d_in[15],
                                      (const float*)d_in[16], (const float*)d_in[17],
                                      (const float*)d_in[18], (const float*)d_in[19],
                                      (float*)d_out);
}

// round 10
// speedup vs baseline: 1.7899x; 1.1421x over previous
#include <cuda_runtime.h>

// ---------------------------------------------------------------------------
// SpatialRangeAttention — GB300 sm_103a
// ---------------------------------------------------------------------------

#define BB   2
#define CC   64
#define HH   112
#define WW   112
#define HWP  (HH*WW)      // 12544
#define NPIX (BB*HWP)     // 25088
#define N2   49

// Scratch
__device__ float g_sem_t[NPIX*CC];   // semantic transposed [pix][c]
__device__ float g_spa_t[NPIX*CC];   // spatial  transposed [pix][c]
__device__ float g_px_cm[NPIX*CC];   // range-projected, CHANNEL-major [b][c][hw]
__device__ float g_nrm[NPIX];        // per-pixel ||px||^2
__device__ float g_comb[NPIX*N2];    // bilateral / final weights [pix][n]

// Interleaved weight buffers (shared by all blocks; L1/L2-resident)
__device__ float2 g_w1r[64*32], g_w2r[64*32];   // range
__device__ float2 g_w1f[113*32], g_w2f[49*32];  // fixup (zero-padded o>=49)
__device__ float2 g_w1o[64*32], g_w2o[64*32];   // output

// 32-FMA block: weight pair a=(w[o],w[o+32]) times 16 pixel x-values
#define ACC32(a, xA, xB, xC, xD)                      \
    y0[0] += a.x*xA.x;  y1[0] += a.y*xA.x;            \
    y0[1] += a.x*xA.y;  y1[1] += a.y*xA.y;            \
    y0[2] += a.x*xA.z;  y1[2] += a.y*xA.z;            \
    y0[3] += a.x*xA.w;  y1[3] += a.y*xA.w;            \
    y0[4] += a.x*xB.x;  y1[4] += a.y*xB.x;            \
    y0[5] += a.x*xB.y;  y1[5] += a.y*xB.y;            \
    y0[6] += a.x*xB.z;  y1[6] += a.y*xB.z;            \
    y0[7] += a.x*xB.w;  y1[7] += a.y*xB.w;            \
    y0[8] += a.x*xC.x;  y1[8] += a.y*xC.x;            \
    y0[9] += a.x*xC.y;  y1[9] += a.y*xC.y;            \
    y0[10]+= a.x*xC.z;  y1[10]+= a.y*xC.z;            \
    y0[11]+= a.x*xC.w;  y1[11]+= a.y*xC.w;            \
    y0[12]+= a.x*xD.x;  y1[12]+= a.y*xD.x;            \
    y0[13]+= a.x*xD.y;  y1[13]+= a.y*xD.y;            \
    y0[14]+= a.x*xD.z;  y1[14]+= a.y*xD.z;            \
    y0[15]+= a.x*xD.w;  y1[15]+= a.y*xD.w;

// ---------------------------------------------------------------------------
// K-1: prep — interleave all conv weights into global float2 buffers
// ---------------------------------------------------------------------------
__global__ __launch_bounds__(256) void k_prep(
    const float* __restrict__ rw1, const float* __restrict__ rw2,
    const float* __restrict__ fw1, const float* __restrict__ fw2,
    const float* __restrict__ ow1, const float* __restrict__ ow2)
{
    int i = blockIdx.x * 256 + threadIdx.x;
    if (i < 2048) {
        int c = i >> 5, l = i & 31;
        g_w1r[i] = make_float2(rw1[l*64 + c], rw1[(l+32)*64 + c]);
        g_w2r[i] = make_float2(rw2[l*64 + c], rw2[(l+32)*64 + c]);
        g_w1o[i] = make_float2(ow1[l*64 + c], ow1[(l+32)*64 + c]);
        g_w2o[i] = make_float2(ow2[l*64 + c], ow2[(l+32)*64 + c]);
    }
    if (i < 113*32) {
        int j = i >> 5, l = i & 31;
        g_w1f[i] = make_float2((l    < N2) ? fw1[l*113 + j]      : 0.f,
                               (l+32 < N2) ? fw1[(l+32)*113 + j] : 0.f);
    }
    if (i < 49*32) {
        int j = i >> 5, l = i & 31;
        g_w2f[i] = make_float2((l    < N2) ? fw2[l*49 + j]      : 0.f,
                               (l+32 < N2) ? fw2[(l+32)*49 + j] : 0.f);
    }
}

// ---------------------------------------------------------------------------
// K0: transpose both inputs [B,C,HW] -> [B*HW, C]
// ---------------------------------------------------------------------------
__global__ __launch_bounds__(256) void k_transpose2(
    const float* __restrict__ sem, const float* __restrict__ spa)
{
    __shared__ float t1[32][33];
    __shared__ float t2[32][33];
    int b  = blockIdx.z;
    int c0 = blockIdx.y * 32;
    int p0 = blockIdx.x * 32;
    int tx = threadIdx.x, ty = threadIdx.y;
    #pragma unroll
    for (int i = ty; i < 32; i += 8) {
        int c = c0 + i, p = p0 + tx;
        t1[i][tx] = sem[(b*CC + c)*HWP + p];
        t2[i][tx] = spa[(b*CC + c)*HWP + p];
    }
    __syncthreads();
    #pragma unroll
    for (int i = ty; i < 32; i += 8) {
        int p = p0 + i, c = c0 + tx;
        g_sem_t[(b*HWP + p)*CC + c] = t1[tx][i];
        g_spa_t[(b*HWP + p)*CC + c] = t2[tx][i];
    }
}

// ---------------------------------------------------------------------------
// K1: range_proj. 16 px/warp, 32 accumulators, weights via LDG.
// smem = xs only (16384B) -> high occupancy.
// ---------------------------------------------------------------------------
__global__ __launch_bounds__(128, 7) void k_range(
    const float* __restrict__ b1, const float* __restrict__ g,
    const float* __restrict__ be, const float* __restrict__ b2)
{
    extern __shared__ float sm[];
    float* xs = sm;                          // [4 warps][64 rows][16 px]
    int tid = threadIdx.x, lane = tid & 31, w = tid >> 5;

    float b1_0 = b1[lane], b1_1 = b1[lane+32];
    float g_0  = g[lane],  g_1  = g[lane+32];
    float be_0 = be[lane], be_1 = be[lane+32];
    float b2_0 = b2[lane], b2_1 = b2[lane+32];

    int pbase = blockIdx.x * 64 + w * 16;
    float* xw = xs + w * 1024;

    // stage 16 pixels transposed: lane q owns pixel q; halves split channels
    {
        int q = lane & 15, half = lane >> 4;
        const float* semp = g_sem_t + (pbase + q)*CC;
        int c0 = half * 32;
        for (int i = 0; i < 32; i++) {
            int ii = half ? (i ^ 1) : i;      // parity stagger -> conflict-free
            int c = c0 + ii;
            xw[c*16 + q] = semp[c];
        }
    }
    __syncwarp();

    float y0[16], y1[16];
    #pragma unroll
    for (int q = 0; q < 16; q++) { y0[q] = b1_0; y1[q] = b1_1; }

    #pragma unroll 2
    for (int c = 0; c < 64; c++) {
        float2 a = __ldg(&g_w1r[c*32 + lane]);
        float4 xA = *(const float4*)(xw + c*16);
        float4 xB = *(const float4*)(xw + c*16 + 4);
        float4 xC = *(const float4*)(xw + c*16 + 8);
        float4 xD = *(const float4*)(xw + c*16 + 12);
        ACC32(a, xA, xB, xC, xD)
    }

    // LN + SiLU per pixel
    {
        float h0[16], h1[16];
        #pragma unroll
        for (int q = 0; q < 16; q++) {
            float s = y0[q] + y1[q];
            float t = y0[q]*y0[q] + y1[q]*y1[q];
            #pragma unroll
            for (int o = 16; o; o >>= 1) {
                s += __shfl_xor_sync(0xffffffffu, s, o);
                t += __shfl_xor_sync(0xffffffffu, t, o);
            }
            float mean = s * (1.f/64.f);
            float rstd = rsqrtf(t * (1.f/64.f) - mean*mean + 1e-6f);
            float a0 = g_0 * (y0[q]-mean) * rstd + be_0;
            float a1 = g_1 * (y1[q]-mean) * rstd + be_1;
            h0[q] = a0 / (1.f + __expf(-a0));
            h1[q] = a1 / (1.f + __expf(-a1));
        }
        __syncwarp();
        *(float4*)&xw[lane*16]          = make_float4(h0[0],h0[1],h0[2],h0[3]);
        *(float4*)&xw[lane*16 + 4]      = make_float4(h0[4],h0[5],h0[6],h0[7]);
        *(float4*)&xw[lane*16 + 8]      = make_float4(h0[8],h0[9],h0[10],h0[11]);
        *(float4*)&xw[lane*16 + 12]     = make_float4(h0[12],h0[13],h0[14],h0[15]);
        *(float4*)&xw[(lane+32)*16]     = make_float4(h1[0],h1[1],h1[2],h1[3]);
        *(float4*)&xw[(lane+32)*16 + 4] = make_float4(h1[4],h1[5],h1[6],h1[7]);
        *(float4*)&xw[(lane+32)*16 + 8] = make_float4(h1[8],h1[9],h1[10],h1[11]);
        *(float4*)&xw[(lane+32)*16 +12] = make_float4(h1[12],h1[13],h1[14],h1[15]);
        __syncwarp();
    }

    #pragma unroll
    for (int q = 0; q < 16; q++) { y0[q] = b2_0; y1[q] = b2_1; }
    #pragma unroll 2
    for (int c = 0; c < 64; c++) {
        float2 a = __ldg(&g_w2r[c*32 + lane]);
        float4 xA = *(const float4*)(xw + c*16);
        float4 xB = *(const float4*)(xw + c*16 + 4);
        float4 xC = *(const float4*)(xw + c*16 + 8);
        float4 xD = *(const float4*)(xw + c*16 + 12);
        ACC32(a, xA, xB, xC, xD)
    }

    // norms per pixel
    #pragma unroll
    for (int q = 0; q < 16; q++) {
        float t = y0[q]*y0[q] + y1[q]*y1[q];
        #pragma unroll
        for (int o = 16; o; o >>= 1) t += __shfl_xor_sync(0xffffffffu, t, o);
        if (lane == 0) g_nrm[pbase + q] = t;
    }
    // channel-major stores: 16 consecutive pixels -> 4x STG.128 per half
    {
        int b = pbase / HWP, pp = pbase % HWP;
        float* d0 = &g_px_cm[(size_t)(b*CC + lane)*HWP + pp];
        *(float4*)d0        = make_float4(y0[0],y0[1],y0[2],y0[3]);
        *(float4*)(d0 + 4)  = make_float4(y0[4],y0[5],y0[6],y0[7]);
        *(float4*)(d0 + 8)  = make_float4(y0[8],y0[9],y0[10],y0[11]);
        *(float4*)(d0 + 12) = make_float4(y0[12],y0[13],y0[14],y0[15]);
        float* d1 = &g_px_cm[(size_t)(b*CC + lane + 32)*HWP + pp];
        *(float4*)d1        = make_float4(y1[0],y1[1],y1[2],y1[3]);
        *(float4*)(d1 + 4)  = make_float4(y1[4],y1[5],y1[6],y1[7]);
        *(float4*)(d1 + 8)  = make_float4(y1[8],y1[9],y1[10],y1[11]);
        *(float4*)(d1 + 12) = make_float4(y1[12],y1[13],y1[14],y1[15]);
    }
}

// ---------------------------------------------------------------------------
// K2: bilateral via dot-form: dist2 = |n|^2+|c|^2-2dot. Warp = (32 pixels, dy).
// ---------------------------------------------------------------------------
__global__ __launch_bounds__(256) void k_bilateral(const float* __restrict__ sigma)
{
    int wid  = (blockIdx.x << 3) + (threadIdx.x >> 5);
    int lane = threadIdx.x & 31;
    int gpix = wid / 7;
    int dyi  = wid - gpix*7;
    int dy   = dyi - 3;

    int p  = (gpix << 5) + lane;
    int b  = p / HWP, pp = p % HWP, yy = pp / WW, xx = pp % WW;
    int ny = yy + dy;
    bool rowok = ((unsigned)ny < HH);
    int nrow = (rowok ? ny : yy) * WW;

    const float* base = g_px_cm + (size_t)b * (CC*HWP);

    int off[7]; unsigned okm = 0;
    #pragma unroll
    for (int i = 0; i < 7; i++) {
        int nx = xx + i - 3;
        bool o = rowok & ((unsigned)nx < WW);
        okm |= (o ? 1u : 0u) << i;
        off[i] = nrow + (o ? nx : xx);
    }

    float acc[7] = {0.f,0.f,0.f,0.f,0.f,0.f,0.f};
    #pragma unroll 4
    for (int c = 0; c < CC; c++) {
        const float* rc = base + c*HWP;
        float cv = rc[pp];
        #pragma unroll
        for (int i = 0; i < 7; i++) acc[i] += cv * rc[off[i]];
    }

    float nc = g_nrm[p];
    float sg = *sigma;
    float is2 = 0.5f / (sg*sg);
    float* outp = &g_comb[p*N2 + dyi*7];
    const float* nrmb = &g_nrm[b*HWP];
    #pragma unroll
    for (int i = 0; i < 7; i++) {
        float res = 0.f;
        if ((okm >> i) & 1u) {
            float d2 = fmaxf(nrmb[off[i]] + nc - 2.f*acc[i], 0.f);
            float fdx = (float)(i - 3);
            res = __expf(-d2*(1.f/128.f) - ((float)(dy*dy) + fdx*fdx)*is2);
        }
        outp[i] = res;
    }
}

// ---------------------------------------------------------------------------
// K3a: fixup. 16 px/warp, 32 accumulators, weights via LDG.
// smem = xs only (28928B) -> 6 blocks/SM.
// ---------------------------------------------------------------------------
__global__ __launch_bounds__(128, 6) void k_fixup(
    const float* __restrict__ b1, const float* __restrict__ g,
    const float* __restrict__ be, const float* __restrict__ b2)
{
    extern __shared__ float sm[];
    float* xs = sm;                          // [4 warps][113][16]
    int tid = threadIdx.x, lane = tid & 31, w = tid >> 5;

    const bool has2 = (lane + 32) < N2;  // lane < 17
    float b1_0 = (lane < N2) ? b1[lane] : 0.f;
    float b1_1 = has2 ? b1[lane+32] : 0.f;
    float g_0  = (lane < N2) ? g[lane]  : 0.f;
    float g_1  = has2 ? g[lane+32]  : 0.f;
    float be_0 = (lane < N2) ? be[lane] : 0.f;
    float be_1 = has2 ? be[lane+32] : 0.f;
    float b2_0 = (lane < N2) ? b2[lane] : 0.f;
    float b2_1 = has2 ? b2[lane+32] : 0.f;

    int pbase = blockIdx.x * 64 + w * 16;
    float* xw = xs + w * 1808;

    // stage transposed: lane q owns pixel q; halves split j range
    {
        int q = lane & 15, half = lane >> 4;
        int p = pbase + q;
        const float* combp = g_comb + p*N2;
        const float* semp  = g_sem_t + p*CC;
        if (half == 0) {
            for (int j = 0; j < 57; j++) {
                float v = (j < N2) ? combp[j] : semp[j - N2];
                xw[j*16 + q] = v;
            }
        } else {
            for (int j = 57; j < 113; j++)
                xw[j*16 + q] = semp[j - N2];   // j >= 57 is always sem
        }
    }
    __syncwarp();

    float y0[16], y1[16];
    #pragma unroll
    for (int q = 0; q < 16; q++) { y0[q] = b1_0; y1[q] = b1_1; }

    #pragma unroll 2
    for (int j = 0; j < 113; j++) {
        float2 a = __ldg(&g_w1f[j*32 + lane]);
        float4 xA = *(const float4*)(xw + j*16);
        float4 xB = *(const float4*)(xw + j*16 + 4);
        float4 xC = *(const float4*)(xw + j*16 + 8);
        float4 xD = *(const float4*)(xw + j*16 + 12);
        ACC32(a, xA, xB, xC, xD)
    }

    // LN(49) + SiLU per pixel
    {
        float h0[16], h1[16];
        #pragma unroll
        for (int q = 0; q < 16; q++) {
            float s = y0[q] + (has2 ? y1[q] : 0.f);
            float t = y0[q]*y0[q] + (has2 ? y1[q]*y1[q] : 0.f);
            #pragma unroll
            for (int o = 16; o; o >>= 1) {
                s += __shfl_xor_sync(0xffffffffu, s, o);
                t += __shfl_xor_sync(0xffffffffu, t, o);
            }
            float mean = s * (1.f/49.f);
            float rstd = rsqrtf(t * (1.f/49.f) - mean*mean + 1e-6f);
            float a0 = g_0 * (y0[q]-mean) * rstd + be_0;
            float a1 = g_1 * (y1[q]-mean) * rstd + be_1;
            h0[q] = a0 / (1.f + __expf(-a0));
            h1[q] = a1 / (1.f + __expf(-a1));
        }
        __syncwarp();
        *(float4*)&xw[lane*16]      = make_float4(h0[0],h0[1],h0[2],h0[3]);
        *(float4*)&xw[lane*16 + 4]  = make_float4(h0[4],h0[5],h0[6],h0[7]);
        *(float4*)&xw[lane*16 + 8]  = make_float4(h0[8],h0[9],h0[10],h0[11]);
        *(float4*)&xw[lane*16 + 12] = make_float4(h0[12],h0[13],h0[14],h0[15]);
        if (has2) {
            *(float4*)&xw[(lane+32)*16]      = make_float4(h1[0],h1[1],h1[2],h1[3]);
            *(float4*)&xw[(lane+32)*16 + 4]  = make_float4(h1[4],h1[5],h1[6],h1[7]);
            *(float4*)&xw[(lane+32)*16 + 8]  = make_float4(h1[8],h1[9],h1[10],h1[11]);
            *(float4*)&xw[(lane+32)*16 +12]  = make_float4(h1[12],h1[13],h1[14],h1[15]);
        }
        __syncwarp();
    }

    #pragma unroll
    for (int q = 0; q < 16; q++) { y0[q] = b2_0; y1[q] = b2_1; }
    #pragma unroll 2
    for (int j = 0; j < 49; j++) {
        float2 a = __ldg(&g_w2f[j*32 + lane]);
        float4 xA = *(const float4*)(xw + j*16);
        float4 xB = *(const float4*)(xw + j*16 + 4);
        float4 xC = *(const float4*)(xw + j*16 + 8);
        float4 xD = *(const float4*)(xw + j*16 + 12);
        ACC32(a, xA, xB, xC, xD)
    }

    #pragma unroll
    for (int q = 0; q < 16; q++) {
        int p = pbase + q;
        float cb0 = g_comb[p*N2 + lane];
        float cb1 = has2 ? g_comb[p*N2 + lane + 32] : 0.f;
        float wv0 = cb0 * (1.f + 1.f/(1.f + __expf(-y0[q])));
        float wv1 = has2 ? cb1 * (1.f + 1.f/(1.f + __expf(-y1[q]))) : 0.f;
        float ss = wv0 + wv1;
        #pragma unroll
        for (int o = 16; o; o >>= 1) ss += __shfl_xor_sync(0xffffffffu, ss, o);
        float inv = 1.f / (ss + 1e-7f);
        g_comb[p*N2 + lane] = wv0 * inv;
        if (has2) g_comb[p*N2 + lane + 32] = wv1 * inv;
    }
}

// ---------------------------------------------------------------------------
// K3b: weighted neighborhood reduction + output_proj, weights via LDG.
// 8 px/warp; smem = wsb + os (18048B) -> 4 blocks/SM.
// ---------------------------------------------------------------------------
__global__ __launch_bounds__(256, 4) void k_output(
    const float* __restrict__ b1, const float* __restrict__ g,
    const float* __restrict__ be, const float* __restrict__ b2,
    float* __restrict__ out)
{
    extern __shared__ float sm[];
    float* wsb = sm;                        // [8][52]
    float* os  = sm + 416;                  // [8][64][8]
    int tid = threadIdx.x, lane = tid & 31, w = tid >> 5;

    float b1_0 = b1[lane], b1_1 = b1[lane+32];
    float g_0  = g[lane],  g_1  = g[lane+32];
    float be_0 = be[lane], be_1 = be[lane+32];
    float b2_0 = b2[lane], b2_1 = b2[lane+32];

    int pbase = blockIdx.x * 64 + w * 8;
    float* ow   = os  + w * 512;
    float* wrow = wsb + w * 52;

    // Gather: lane owns channels (2*lane, 2*lane+1); clamped, predicate-free
    {
        float a0[8], a1[8];
        for (int q = 0; q < 8; q++) {
            int p = pbase + q;
            int b = p / HWP, pp = p % HWP, yy = pp / WW, xx = pp % WW;

            for (int n = lane; n < N2; n += 32) wrow[n] = g_comb[p*N2 + n];
            __syncwarp();

            float s0 = 0.f, s1 = 0.f;
            int n = 0;
            #pragma unroll
            for (int dy = -3; dy <= 3; dy++) {
                int ny = min(max(yy + dy, 0), HH-1);
                const float* rbase = &g_spa_t[(b*HWP + ny*WW)*CC + lane*2];
                #pragma unroll
                for (int dx = -3; dx <= 3; dx++, n++) {
                    int nx = min(max(xx + dx, 0), WW-1);
                    float wv = wrow[n];                  // 0 for OOB neighbors
                    float2 sv = *(const float2*)(rbase + nx*CC);
                    s0 += sv.x * wv;
                    s1 += sv.y * wv;
                }
            }
            a0[q] = s0; a1[q] = s1;
            __syncwarp();
        }
        *(float4*)&ow[(lane*2)*8]       = make_float4(a0[0],a0[1],a0[2],a0[3]);
        *(float4*)&ow[(lane*2)*8 + 4]   = make_float4(a0[4],a0[5],a0[6],a0[7]);
        *(float4*)&ow[(lane*2+1)*8]     = make_float4(a1[0],a1[1],a1[2],a1[3]);
        *(float4*)&ow[(lane*2+1)*8 + 4] = make_float4(a1[4],a1[5],a1[6],a1[7]);
        __syncwarp();
    }

    float y0[8], y1[8];
    #pragma unroll
    for (int q = 0; q < 8; q++) { y0[q] = b1_0; y1[q] = b1_1; }
    #pragma unroll 4
    for (int c = 0; c < 64; c++) {
        float2 a = __ldg(&g_w1o[c*32 + lane]);
        float4 xa = *(const float4*)(ow + c*8);
        float4 xb = *(const float4*)(ow + c*8 + 4);
        y0[0]+=a.x*xa.x; y1[0]+=a.y*xa.x;
        y0[1]+=a.x*xa.y; y1[1]+=a.y*xa.y;
        y0[2]+=a.x*xa.z; y1[2]+=a.y*xa.z;
        y0[3]+=a.x*xa.w; y1[3]+=a.y*xa.w;
        y0[4]+=a.x*xb.x; y1[4]+=a.y*xb.x;
        y0[5]+=a.x*xb.y; y1[5]+=a.y*xb.y;
        y0[6]+=a.x*xb.z; y1[6]+=a.y*xb.z;
        y0[7]+=a.x*xb.w; y1[7]+=a.y*xb.w;
    }

    {
        float h0[8], h1[8];
        #pragma unroll
        for (int q = 0; q < 8; q++) {
            float s = y0[q] + y1[q];
            float t = y0[q]*y0[q] + y1[q]*y1[q];
            #pragma unroll
            for (int o = 16; o; o >>= 1) {
                s += __shfl_xor_sync(0xffffffffu, s, o);
                t += __shfl_xor_sync(0xffffffffu, t, o);
            }
            float mean = s * (1.f/64.f);
            float rstd = rsqrtf(t * (1.f/64.f) - mean*mean + 1e-6f);
            h0[q] = g_0 * (y0[q]-mean) * rstd + be_0;
            h1[q] = g_1 * (y1[q]-mean) * rstd + be_1;
        }
        __syncwarp();
        *(float4*)&ow[lane*8]          = make_float4(h0[0],h0[1],h0[2],h0[3]);
        *(float4*)&ow[lane*8 + 4]      = make_float4(h0[4],h0[5],h0[6],h0[7]);
        *(float4*)&ow[(lane+32)*8]     = make_float4(h1[0],h1[1],h1[2],h1[3]);
        *(float4*)&ow[(lane+32)*8 + 4] = make_float4(h1[4],h1[5],h1[6],h1[7]);
        __syncwarp();
    }

    #pragma unroll
    for (int q = 0; q < 8; q++) { y0[q] = b2_0; y1[q] = b2_1; }
    #pragma unroll 4
    for (int c = 0; c < 64; c++) {
        float2 a = __ldg(&g_w2o[c*32 + lane]);
        float4 xa = *(const float4*)(ow + c*8);
        float4 xb = *(const float4*)(ow + c*8 + 4);
        y0[0]+=a.x*xa.x; y1[0]+=a.y*xa.x;
        y0[1]+=a.x*xa.y; y1[1]+=a.y*xa.y;
        y0[2]+=a.x*xa.z; y1[2]+=a.y*xa.z;
        y0[3]+=a.x*xa.w; y1[3]+=a.y*xa.w;
        y0[4]+=a.x*xb.x; y1[4]+=a.y*xb.x;
        y0[5]+=a.x*xb.y; y1[5]+=a.y*xb.y;
        y0[6]+=a.x*xb.z; y1[6]+=a.y*xb.z;
        y0[7]+=a.x*xb.w; y1[7]+=a.y*xb.w;
    }

    #pragma unroll
    for (int q = 0; q < 8; q++) {
        int p = pbase + q;
        int b = p / HWP, pp = p % HWP;
        out[(b*CC + lane)*HWP + pp]      = y0[q];
        out[(b*CC + lane + 32)*HWP + pp] = y1[q];
    }
}

// ---------------------------------------------------------------------------
extern "C" void kernel_launch(void* const* d_in, const int* in_sizes, int n_in,
                              void* d_out, int out_size)
{
    const float* spa = (const float*)d_in[0];
    const float* sem = (const float*)d_in[1];

    static bool attr_set = false;
    if (!attr_set) {
        cudaFuncSetAttribute(k_range,  cudaFuncAttributeMaxDynamicSharedMemorySize, 16384);
        cudaFuncSetAttribute(k_fixup,  cudaFuncAttributeMaxDynamicSharedMemorySize, 28928);
        cudaFuncSetAttribute(k_output, cudaFuncAttributeMaxDynamicSharedMemorySize, 18048);
        attr_set = true;
    }

    k_prep<<<15, 256>>>((const float*)d_in[2], (const float*)d_in[6],
                        (const float*)d_in[8], (const float*)d_in[12],
                        (const float*)d_in[14], (const float*)d_in[18]);

    dim3 tg(HWP/32, CC/32, BB), tb(32, 8);
    k_transpose2<<<tg, tb>>>(sem, spa);

    k_range<<<NPIX/64, 128, 16384>>>((const float*)d_in[3],
                                     (const float*)d_in[4], (const float*)d_in[5],
                                     (const float*)d_in[7]);

    // warps = (NPIX/32) * 7 = 5488 ; 8 warps/block -> 686 blocks
    k_bilateral<<<686, 256>>>((const float*)d_in[20]);

    k_fixup<<<NPIX/64, 128, 28928>>>((const float*)d_in[9],
                                     (const float*)d_in[10], (const float*)d_in[11],
                                     (const float*)d_in[13]);

    k_output<<<NPIX/64, 256, 18048>>>((const float*)d_in[15],
                                      (const float*)d_in[16], (const float*)d_in[17],
                                      (const float*)d_in[19],
                                      (float*)d_out);
}